// round 1
// baseline (speedup 1.0000x reference)
#include <cuda_runtime.h>
#include <math.h>

// Problem dims: (1, 1, D=160, H=192, W=160), x fastest.
#define DW 160
#define DH 192
#define DD 160
#define NVOX (DD*DH*DW)

#define TX 32
#define TY 8
#define CZ 32
#define SMW (TX+2)
#define SMH (TY+2)
#define NTHREADS (TX*TY)
#define FEPS 1e-10f

__device__ double g_sum;

__global__ void zero_kernel() { g_sum = 0.0; }

__global__ __launch_bounds__(NTHREADS)
void demons_kernel(const float* __restrict__ Mp,
                   const float* __restrict__ Sp,
                   const float* __restrict__ Fp)
{
    __shared__ float sm[2][2][SMH][SMW];   // [pingpong][M/S][y][x]
    __shared__ float red[NTHREADS];

    const int tx = threadIdx.x, ty = threadIdx.y;
    const int tid = ty * TX + tx;
    const int x = blockIdx.x * TX + tx;
    const int y = blockIdx.y * TY + ty;
    const int zbase = blockIdx.z * CZ;

    // Per-slice separable responses, ring of 3 slices.
    // A = smooth_y (x) diff_x   -> Gx = A(z-1)+A(z)+A(z+1)
    // B = diff_y   (x) smooth_x -> Gy = B(z-1)+B(z)+B(z+1)
    // C = smooth_y (x) box_x    -> Gz = C(z+1)-C(z-1)
    float AM[3], BM[3], CM[3], Mc[3];
    float AS[3], BS[3], CS[3], Sc[3];
    float acc = 0.f;

    for (int j = 0; j <= CZ + 1; ++j) {
        const int s = zbase - 1 + j;        // slice being loaded/filtered
        const int b = j & 1;
        const bool zin = (s >= 0) && (s < DD);

        // ---- load slice s (with +/-1 halo in x,y; zero-pad outside) ----
        #pragma unroll
        for (int i = tid; i < SMH * SMW; i += NTHREADS) {
            const int ly = i / SMW;
            const int lx = i - ly * SMW;
            const int gy = blockIdx.y * TY + ly - 1;
            const int gx = blockIdx.x * TX + lx - 1;
            float mv = 0.f, sv = 0.f;
            if (zin && gy >= 0 && gy < DH && gx >= 0 && gx < DW) {
                const int idx = (s * DH + gy) * DW + gx;
                mv = __ldg(Mp + idx);
                sv = __ldg(Sp + idx);
            }
            sm[b][0][ly][lx] = mv;
            sm[b][1][ly][lx] = sv;
        }
        __syncthreads();

        // ---- in-plane separable responses for this slice ----
        const int r = j % 3;
        {
            float rD0, rD1, rD2, rS0, rS1, rS2, rB0, rB1, rB2;
            float v0, v1, v2;
            v0 = sm[b][0][ty + 0][tx]; v1 = sm[b][0][ty + 0][tx + 1]; v2 = sm[b][0][ty + 0][tx + 2];
            rD0 = v2 - v0; rS0 = v0 + 2.f * v1 + v2; rB0 = v0 + v1 + v2;
            v0 = sm[b][0][ty + 1][tx]; v1 = sm[b][0][ty + 1][tx + 1]; v2 = sm[b][0][ty + 1][tx + 2];
            rD1 = v2 - v0; rS1 = v0 + 2.f * v1 + v2; rB1 = v0 + v1 + v2;
            Mc[r] = v1;
            v0 = sm[b][0][ty + 2][tx]; v1 = sm[b][0][ty + 2][tx + 1]; v2 = sm[b][0][ty + 2][tx + 2];
            rD2 = v2 - v0; rS2 = v0 + 2.f * v1 + v2; rB2 = v0 + v1 + v2;
            AM[r] = rD0 + 2.f * rD1 + rD2;
            BM[r] = rS2 - rS0;
            CM[r] = rB0 + 2.f * rB1 + rB2;
        }
        {
            float rD0, rD1, rD2, rS0, rS1, rS2, rB0, rB1, rB2;
            float v0, v1, v2;
            v0 = sm[b][1][ty + 0][tx]; v1 = sm[b][1][ty + 0][tx + 1]; v2 = sm[b][1][ty + 0][tx + 2];
            rD0 = v2 - v0; rS0 = v0 + 2.f * v1 + v2; rB0 = v0 + v1 + v2;
            v0 = sm[b][1][ty + 1][tx]; v1 = sm[b][1][ty + 1][tx + 1]; v2 = sm[b][1][ty + 1][tx + 2];
            rD1 = v2 - v0; rS1 = v0 + 2.f * v1 + v2; rB1 = v0 + v1 + v2;
            Sc[r] = v1;
            v0 = sm[b][1][ty + 2][tx]; v1 = sm[b][1][ty + 2][tx + 1]; v2 = sm[b][1][ty + 2][tx + 2];
            rD2 = v2 - v0; rS2 = v0 + 2.f * v1 + v2; rB2 = v0 + v1 + v2;
            AS[r] = rD0 + 2.f * rD1 + rD2;
            BS[r] = rS2 - rS0;
            CS[r] = rB0 + 2.f * rB1 + rB2;
        }

        // ---- emit output voxel at z = s-1 once 3 slices are live ----
        if (j >= 2) {
            const int r2 = r;
            const int r1 = (j - 1) % 3;
            const int r0 = (j - 2) % 3;
            const int z = s - 1;

            const float Mx = AM[r0] + AM[r1] + AM[r2];
            const float My = BM[r0] + BM[r1] + BM[r2];
            const float Mz = CM[r2] - CM[r0];
            const float Sx = AS[r0] + AS[r1] + AS[r2];
            const float Sy = BS[r0] + BS[r1] + BS[r2];
            const float Sz = CS[r2] - CS[r0];

            const float Id  = Mc[r1] - Sc[r1];
            const float Id2 = Id * Id;
            const float dS = Sx * Sx + Sy * Sy + Sz * Sz + Id2 + FEPS;
            const float dM = Mx * Mx + My * My + Mz * Mz + Id2 + FEPS;
            const float invS = 1.f / dS;
            const float invM = 1.f / dM;
            const float Ux = Id * (Sx * invS + Mx * invM);
            const float Uy = Id * (Sy * invS + My * invM);
            const float Uz = Id * (Sz * invS + Mz * invM);

            const float izd = 1.f / (Uz + FEPS);
            const float dxz = atanf(Ux * izd);
            const float dyz = atanf(Uy * izd);

            const int idx = (z * DH + y) * DW + x;
            const float fx = __ldg(Fp + idx);
            const float fy = __ldg(Fp + NVOX + idx);
            const float fz = __ldg(Fp + 2 * NVOX + idx);
            const float ifz = 1.f / (fz + FEPS);
            const float fxz = atanf(fx * ifz);
            const float fyz = atanf(fy * ifz);

            const float e1 = fxz - dxz;
            const float e2 = fyz - dyz;
            acc += e1 * e1 + e2 * e2;
        }
    }

    // ---- block reduction ----
    red[tid] = acc;
    __syncthreads();
    #pragma unroll
    for (int off = NTHREADS / 2; off > 0; off >>= 1) {
        if (tid < off) red[tid] += red[tid + off];
        __syncthreads();
    }
    if (tid == 0) atomicAdd(&g_sum, (double)red[0]);
}

__global__ void final_kernel(float* out)
{
    out[0] = (float)(g_sum / (double)NVOX);
}

extern "C" void kernel_launch(void* const* d_in, const int* in_sizes, int n_in,
                              void* d_out, int out_size)
{
    const float* Mp = (const float*)d_in[0];
    const float* Sp = (const float*)d_in[1];
    const float* Fp = (const float*)d_in[2];
    float* out = (float*)d_out;

    zero_kernel<<<1, 1>>>();
    dim3 grid(DW / TX, DH / TY, DD / CZ);   // (5, 24, 5)
    dim3 block(TX, TY, 1);                  // (32, 8)
    demons_kernel<<<grid, block>>>(Mp, Sp, Fp);
    final_kernel<<<1, 1>>>(out);
}

// round 2
// speedup vs baseline: 1.5625x; 1.5625x over previous
#include <cuda_runtime.h>
#include <math.h>

// dims: (1,1,D=160,H=192,W=160), x fastest
#define DW 160
#define DH 192
#define DD 160
#define SLICE (DH*DW)
#define NVOX (DD*SLICE)

#define TX 32
#define TY 8
#define CZ 32
#define SMW (TX+2)
#define SMH (TY+2)
#define NTHREADS (TX*TY)
#define GXD (DW/TX)   // 5
#define GYD (DH/TY)   // 24
#define GZD (DD/CZ)   // 5
#define NBLOCKS (GXD*GYD*GZD)   // 600
#define FEPS 1e-10f

__device__ float g_partial[NBLOCKS];
__device__ unsigned int g_count = 0;

__global__ __launch_bounds__(NTHREADS)
void demons_kernel(const float* __restrict__ Mp,
                   const float* __restrict__ Sp,
                   const float* __restrict__ Fp,
                   float* __restrict__ out)
{
    __shared__ float2 sm[2][SMH][SMW];      // .x = M, .y = S
    __shared__ float warpred[NTHREADS / 32];
    __shared__ bool isLast;

    const int tx = threadIdx.x, ty = threadIdx.y;
    const int tid = ty * TX + tx;
    const int x = blockIdx.x * TX + tx;
    const int y = blockIdx.y * TY + ty;
    const int zbase = blockIdx.z * CZ;
    const int bid = blockIdx.x + GXD * (blockIdx.y + GYD * blockIdx.z);

    // ---- halo-load mapping (z-invariant): each thread covers <=2 of 340 slots ----
    const int ly0 = tid / SMW, lx0 = tid - ly0 * SMW;
    const int gy0 = blockIdx.y * TY + ly0 - 1;
    const int gx0 = blockIdx.x * TX + lx0 - 1;
    const bool v0 = (gy0 >= 0) && (gy0 < DH) && (gx0 >= 0) && (gx0 < DW);
    const int off0 = v0 ? (gy0 * DW + gx0) : 0;

    const int i1 = tid + NTHREADS;
    const bool has1 = (i1 < SMH * SMW);
    const int ly1 = has1 ? (i1 / SMW) : 0;
    const int lx1 = has1 ? (i1 - ly1 * SMW) : 0;
    const int gy1 = blockIdx.y * TY + ly1 - 1;
    const int gx1 = blockIdx.x * TX + lx1 - 1;
    const bool v1 = has1 && (gy1 >= 0) && (gy1 < DH) && (gx1 >= 0) && (gx1 < DW);
    const int off1 = v1 ? (gy1 * DW + gx1) : 0;

    // ---- per-slice separable responses, explicit register ring (no spills) ----
    // A = smooth_y x diff_x ; B = diff_y x smooth_x ; C = smooth_y x box_x
    float AM0, AM1, AM2, BM0, BM1, BM2, CM0, CM1, CM2, Mc0, Mc1, Mc2;
    float AS0, AS1, AS2, BS0, BS1, BS2, CS0, CS1, CS2, Sc0, Sc1, Sc2;
    AM0=AM1=BM0=BM1=CM0=CM1=Mc0=Mc1=0.f;
    AS0=AS1=BS0=BS1=CS0=CS1=Sc0=Sc1=0.f;
    float acc = 0.f;

    // prefetch slice zbase-1 (iteration j=0)
    float pm0, ps0, pm1, ps1;
    {
        const int s = zbase - 1;
        const bool zin = (s >= 0);
        const int base = s * SLICE;
        pm0 = (zin && v0) ? __ldg(Mp + base + off0) : 0.f;
        ps0 = (zin && v0) ? __ldg(Sp + base + off0) : 0.f;
        pm1 = (zin && v1) ? __ldg(Mp + base + off1) : 0.f;
        ps1 = (zin && v1) ? __ldg(Sp + base + off1) : 0.f;
    }

    #pragma unroll 2
    for (int j = 0; j <= CZ + 1; ++j) {
        const int b = j & 1;

        // store prefetched slice into smem
        sm[b][ly0][lx0] = make_float2(pm0, ps0);
        if (has1) sm[b][ly1][lx1] = make_float2(pm1, ps1);

        // prefetch next slice (LDG in flight across sync+compute)
        if (j <= CZ) {
            const int s = zbase + j;
            const bool zin = (s < DD);
            const int base = s * SLICE;
            pm0 = (zin && v0) ? __ldg(Mp + base + off0) : 0.f;
            ps0 = (zin && v0) ? __ldg(Sp + base + off0) : 0.f;
            pm1 = (zin && v1) ? __ldg(Mp + base + off1) : 0.f;
            ps1 = (zin && v1) ? __ldg(Sp + base + off1) : 0.f;
        }
        __syncthreads();

        // in-plane separable responses for this slice (float2: M=.x, S=.y)
        const float2 a0 = sm[b][ty + 0][tx], a1 = sm[b][ty + 0][tx + 1], a2 = sm[b][ty + 0][tx + 2];
        const float2 q0 = sm[b][ty + 1][tx], q1 = sm[b][ty + 1][tx + 1], q2 = sm[b][ty + 1][tx + 2];
        const float2 c0 = sm[b][ty + 2][tx], c1 = sm[b][ty + 2][tx + 1], c2 = sm[b][ty + 2][tx + 2];

        {   // M
            const float rD0 = a2.x - a0.x, rSm0 = a0.x + 2.f * a1.x + a2.x, rB0 = a0.x + a1.x + a2.x;
            const float rD1 = q2.x - q0.x, rSm1 = q0.x + 2.f * q1.x + q2.x, rB1 = q0.x + q1.x + q2.x;
            const float rD2 = c2.x - c0.x, rSm2 = c0.x + 2.f * c1.x + c2.x, rB2 = c0.x + c1.x + c2.x;
            AM2 = rD0 + 2.f * rD1 + rD2;
            BM2 = rSm2 - rSm0;
            CM2 = rB0 + 2.f * rB1 + rB2;
            Mc2 = q1.x;
        }
        {   // S
            const float rD0 = a2.y - a0.y, rSm0 = a0.y + 2.f * a1.y + a2.y, rB0 = a0.y + a1.y + a2.y;
            const float rD1 = q2.y - q0.y, rSm1 = q0.y + 2.f * q1.y + q2.y, rB1 = q0.y + q1.y + q2.y;
            const float rD2 = c2.y - c0.y, rSm2 = c0.y + 2.f * c1.y + c2.y, rB2 = c0.y + c1.y + c2.y;
            AS2 = rD0 + 2.f * rD1 + rD2;
            BS2 = rSm2 - rSm0;
            CS2 = rB0 + 2.f * rB1 + rB2;
            Sc2 = q1.y;
        }

        // emit output voxel z = zbase + j - 2 once three slices are live
        if (j >= 2) {
            const int z = zbase + j - 2;

            const float Mx = AM0 + AM1 + AM2;
            const float My = BM0 + BM1 + BM2;
            const float Mz = CM2 - CM0;
            const float Sx = AS0 + AS1 + AS2;
            const float Sy = BS0 + BS1 + BS2;
            const float Sz = CS2 - CS0;

            const float Id  = Mc1 - Sc1;
            const float Id2 = Id * Id;
            const float dS = Sx * Sx + Sy * Sy + Sz * Sz + Id2 + FEPS;
            const float dM = Mx * Mx + My * My + Mz * Mz + Id2 + FEPS;
            const float invS = 1.f / dS;
            const float invM = 1.f / dM;
            const float Ux = Id * (Sx * invS + Mx * invM);
            const float Uy = Id * (Sy * invS + My * invM);
            const float Uz = Id * (Sz * invS + Mz * invM);

            const float izd = 1.f / (Uz + FEPS);
            const float dxz = atanf(Ux * izd);
            const float dyz = atanf(Uy * izd);

            const int idx = (z * DH + y) * DW + x;
            const float fx = __ldg(Fp + idx);
            const float fy = __ldg(Fp + NVOX + idx);
            const float fz = __ldg(Fp + 2 * NVOX + idx);
            const float ifz = 1.f / (fz + FEPS);
            const float fxz = atanf(fx * ifz);
            const float fyz = atanf(fy * ifz);

            const float e1 = fxz - dxz;
            const float e2 = fyz - dyz;
            acc += e1 * e1 + e2 * e2;
        }

        // shift register rings
        AM0 = AM1; AM1 = AM2;  BM0 = BM1; BM1 = BM2;
        CM0 = CM1; CM1 = CM2;  Mc0 = Mc1; Mc1 = Mc2;
        AS0 = AS1; AS1 = AS2;  BS0 = BS1; BS1 = BS2;
        CS0 = CS1; CS1 = CS2;  Sc0 = Sc1; Sc1 = Sc2;
    }

    // ---- block reduction: warp shuffle + smem ----
    #pragma unroll
    for (int o = 16; o > 0; o >>= 1) acc += __shfl_xor_sync(0xffffffffu, acc, o);
    if ((tid & 31) == 0) warpred[tid >> 5] = acc;
    __syncthreads();
    if (tid == 0) {
        float v = 0.f;
        #pragma unroll
        for (int w = 0; w < NTHREADS / 32; ++w) v += warpred[w];
        g_partial[bid] = v;
        __threadfence();
        const unsigned int c = atomicAdd(&g_count, 1u);
        isLast = (c == (unsigned)(NBLOCKS - 1));
    }
    __syncthreads();

    // ---- last block finishes: reduce 600 partials, write scalar, reset counter ----
    if (isLast) {
        float s = 0.f;
        for (int i = tid; i < NBLOCKS; i += NTHREADS) s += g_partial[i];
        #pragma unroll
        for (int o = 16; o > 0; o >>= 1) s += __shfl_xor_sync(0xffffffffu, s, o);
        if ((tid & 31) == 0) warpred[tid >> 5] = s;
        __syncthreads();
        if (tid == 0) {
            float t = 0.f;
            #pragma unroll
            for (int w = 0; w < NTHREADS / 32; ++w) t += warpred[w];
            out[0] = t / (float)NVOX;
            g_count = 0u;    // reset for next (deterministic) launch
        }
    }
}

extern "C" void kernel_launch(void* const* d_in, const int* in_sizes, int n_in,
                              void* d_out, int out_size)
{
    const float* Mp = (const float*)d_in[0];
    const float* Sp = (const float*)d_in[1];
    const float* Fp = (const float*)d_in[2];
    float* out = (float*)d_out;

    dim3 grid(GXD, GYD, GZD);   // (5, 24, 5) = 600 blocks
    dim3 block(TX, TY, 1);      // (32, 8)
    demons_kernel<<<grid, block>>>(Mp, Sp, Fp, out);
}